// round 15
// baseline (speedup 1.0000x reference)
#include <cuda_runtime.h>
#include <math.h>
#include <stdint.h>

// ---------------- problem constants ----------------
#define BZ     32
#define DM     768
#define NH     12
#define DH     64
#define LSEQ   197
#define NPATCH 196
#define LTOP   101
#define KTOP   100
#define M1     (BZ*LSEQ)     // 6304
#define M2     (BZ*LTOP)     // 3232
#define MP     (BZ*NPATCH)   // 6272

// ---------------- device scratch (no allocs allowed) ----------------
__device__ __align__(128) float g_t[M1*DM];
__device__ __align__(128) float g_ln[M1*DM];
__device__ __align__(128) float g_qkv[M1*3*DM];
__device__ __align__(128) float g_att[M1*DM];
__device__ __align__(128) float g_h[M1*4*DM];
__device__ __align__(128) float g_pat[MP*DM];
__device__ __align__(128) float g_tmp[MP*DM];
__device__ __align__(128) float g_kq[M1*DM];
__device__ __align__(128) float g_q0[BZ*DM];
__device__ __align__(128) float g_sc[BZ*NPATCH];
__device__ __align__(128) int   g_idx[BZ*KTOP];
__device__ __align__(128) float g_inp[M2*DM];

// ---------------- im2col: x(B,3,224,224) -> patches (B*196, 768) ----------------
__global__ void im2col_k(const float* __restrict__ x, float* __restrict__ p) {
    int idx = blockIdx.x * blockDim.x + threadIdx.x;
    if (idx >= MP * DM) return;
    int d  = idx % DM;
    int m  = idx / DM;
    int b  = m / NPATCH, pp = m % NPATCH;
    int hp = pp / 14,    wp = pp % 14;
    int c  = d >> 8;
    int rem = d & 255;
    int py = rem >> 4, px = rem & 15;
    p[idx] = x[(((size_t)(b*3 + c)*224 + hp*16 + py))*224 + wp*16 + px];
}

// ---------------- assemble: cls + patches + pos_emb -> t ----------------
__global__ void assemble_k(const float* __restrict__ tmp, const float* __restrict__ cls,
                           const float* __restrict__ pos, float* __restrict__ t) {
    int idx = blockIdx.x * blockDim.x + threadIdx.x;
    if (idx >= M1 * DM) return;
    int d = idx % DM;
    int m = idx / DM;
    int b = m / LSEQ, l = m % LSEQ;
    float v;
    if (l == 0) v = cls[d] + pos[d];
    else        v = tmp[((size_t)b*NPATCH + (l-1))*DM + d] + pos[(size_t)l*DM + d];
    t[idx] = v;
}

// ---------------- layernorm ----------------
__global__ void ln_k(const float* __restrict__ x, const float* __restrict__ gs,
                     const float* __restrict__ bs, float* __restrict__ y) {
    int row = blockIdx.x;
    int tid = threadIdx.x;
    const float* xr = x + (size_t)row * DM;
    float v0 = xr[tid], v1 = xr[tid+256], v2 = xr[tid+512];
    __shared__ float red[256];
    red[tid] = v0 + v1 + v2;
    __syncthreads();
    for (int s = 128; s > 0; s >>= 1) { if (tid < s) red[tid] += red[tid+s]; __syncthreads(); }
    float mean = red[0] * (1.f/768.f);
    __syncthreads();
    float d0 = v0-mean, d1 = v1-mean, d2 = v2-mean;
    red[tid] = d0*d0 + d1*d1 + d2*d2;
    __syncthreads();
    for (int s = 128; s > 0; s >>= 1) { if (tid < s) red[tid] += red[tid+s]; __syncthreads(); }
    float rstd = rsqrtf(red[0] * (1.f/768.f) + 1e-6f);
    float* yr = y + (size_t)row * DM;
    yr[tid]     = d0*rstd*gs[tid]     + bs[tid];
    yr[tid+256] = d1*rstd*gs[tid+256] + bs[tid+256];
    yr[tid+512] = d2*rstd*gs[tid+512] + bs[tid+512];
}

// ---------------- fp32 GEMM: scalar FFMA, double-buffered, tunable N-tile ----------------
// C[M,N] = A[M,K]*W + bias (+gelu | +residual). Bitwise identical to the
// known-good scalar fp32 version: each output element is a single k-ascending
// fp32 FMA chain. N-tile TN is chosen per GEMM for wave-quantization (M/N
// tiling does not touch the k-chain, so results are bit-identical).
// Tile 128 x TN, 256 threads, per-thread 8 x (TN/16). K % 16 == 0, N % TN == 0.
// TRANSB path (W as [N,K]) only instantiated with TN=128.
// EPI: 0 = bias, 1 = bias+gelu(exact), 2 = bias+residual
template<int EPI, bool TRANSB, int TN>
__global__ __launch_bounds__(256, 2) void gemm_s(
    const float* __restrict__ A, const float* __restrict__ W,
    const float* __restrict__ bias, const float* __restrict__ res,
    float* __restrict__ C, int M, int N, int K, int ldw)
{
    constexpr int WN   = TN / 16;        // per-thread n width: 8 / 6 / 4
    constexpr int BSTR = TN + 4;         // smem B row stride (x4B % 16 == 0)
    __shared__ float As[2][16][132];     // [buf][k][m]
    __shared__ float Bs[2][16][BSTR];    // [buf][k][n]
    const int tid = threadIdx.x;
    const int tx = tid & 15;             // n: tx*WN
    const int ty = tid >> 4;             // m: ty*8
    const int bm = blockIdx.y * 128, bn = blockIdx.x * TN;

    float acc[8][WN];
#pragma unroll
    for (int i = 0; i < 8; i++)
#pragma unroll
        for (int j = 0; j < WN; j++) acc[i][j] = 0.f;

    // A loader: 128 rows x 16 k; thread: row=tid>>1, 8 k at (tid&1)*8
    const int rowA = tid >> 1;
    const int kA   = (tid & 1) * 8;
    const int grA  = bm + rowA;
    const bool avalid = (grA < M);
    // B loader (no trans): 16 k x TN n; thread: k=tid>>4, WN n at (tid&15)*WN
    const int kB = tid >> 4;
    const int nB = (tid & 15) * WN;

    float av[8];
    float bv[8];                         // first WN entries used

    auto load_regs = [&](int k0) {
        if (avalid) {
            const float* ap = A + (size_t)grA * K + k0 + kA;
            float4 a0 = *reinterpret_cast<const float4*>(ap);
            float4 a1 = *reinterpret_cast<const float4*>(ap + 4);
            av[0]=a0.x; av[1]=a0.y; av[2]=a0.z; av[3]=a0.w;
            av[4]=a1.x; av[5]=a1.y; av[6]=a1.z; av[7]=a1.w;
        } else {
#pragma unroll
            for (int q = 0; q < 8; q++) av[q] = 0.f;
        }
        if (!TRANSB) {
            const float* wp = W + (size_t)(k0 + kB) * ldw + bn + nB;
            if (WN == 8) {
                float4 b0 = *reinterpret_cast<const float4*>(wp);
                float4 b1 = *reinterpret_cast<const float4*>(wp + 4);
                bv[0]=b0.x; bv[1]=b0.y; bv[2]=b0.z; bv[3]=b0.w;
                bv[4]=b1.x; bv[5]=b1.y; bv[6]=b1.z; bv[7]=b1.w;
            } else if (WN == 6) {
                float2 b0 = *reinterpret_cast<const float2*>(wp);
                float2 b1 = *reinterpret_cast<const float2*>(wp + 2);
                float2 b2 = *reinterpret_cast<const float2*>(wp + 4);
                bv[0]=b0.x; bv[1]=b0.y; bv[2]=b1.x; bv[3]=b1.y; bv[4]=b2.x; bv[5]=b2.y;
            } else {
                float4 b0 = *reinterpret_cast<const float4*>(wp);
                bv[0]=b0.x; bv[1]=b0.y; bv[2]=b0.z; bv[3]=b0.w;
            }
        } else {
            // TN == 128 only: W[N,K], row bn+rowA, cols k0+kA..+7
            const float* wp = W + (size_t)(bn + rowA) * ldw + k0 + kA;
            float4 b0 = *reinterpret_cast<const float4*>(wp);
            float4 b1 = *reinterpret_cast<const float4*>(wp + 4);
            bv[0]=b0.x; bv[1]=b0.y; bv[2]=b0.z; bv[3]=b0.w;
            bv[4]=b1.x; bv[5]=b1.y; bv[6]=b1.z; bv[7]=b1.w;
        }
    };
    auto store_smem = [&](int s) {
#pragma unroll
        for (int q = 0; q < 8; q++) As[s][kA+q][rowA] = av[q];
        if (!TRANSB) {
            float* bp = &Bs[s][kB][nB];
            if (WN == 8) {
                *reinterpret_cast<float4*>(bp)     = make_float4(bv[0],bv[1],bv[2],bv[3]);
                *reinterpret_cast<float4*>(bp + 4) = make_float4(bv[4],bv[5],bv[6],bv[7]);
            } else if (WN == 6) {
                *reinterpret_cast<float2*>(bp)     = make_float2(bv[0],bv[1]);
                *reinterpret_cast<float2*>(bp + 2) = make_float2(bv[2],bv[3]);
                *reinterpret_cast<float2*>(bp + 4) = make_float2(bv[4],bv[5]);
            } else {
                *reinterpret_cast<float4*>(bp)     = make_float4(bv[0],bv[1],bv[2],bv[3]);
            }
        } else {
#pragma unroll
            for (int q = 0; q < 8; q++) Bs[s][kA+q][rowA] = bv[q];
        }
    };

    // ---- prologue: tile 0 into buffer 0 ----
    load_regs(0);
    store_smem(0);
    __syncthreads();

    int cur = 0;
    for (int k0 = 0; k0 < K; k0 += 16) {
        const bool has_next = (k0 + 16 < K);
        if (has_next) load_regs(k0 + 16);   // LDGs in flight during compute

#pragma unroll
        for (int k = 0; k < 16; k++) {
            float4 a0 = *reinterpret_cast<const float4*>(&As[cur][k][ty*8]);
            float4 a1 = *reinterpret_cast<const float4*>(&As[cur][k][ty*8+4]);
            float ra[8] = {a0.x,a0.y,a0.z,a0.w,a1.x,a1.y,a1.z,a1.w};
            float rb[WN];
            const float* bp = &Bs[cur][k][tx*WN];
            if (WN == 8) {
                float4 b0 = *reinterpret_cast<const float4*>(bp);
                float4 b1 = *reinterpret_cast<const float4*>(bp + 4);
                rb[0]=b0.x; rb[1]=b0.y; rb[2]=b0.z; rb[3]=b0.w;
                rb[4]=b1.x; rb[5]=b1.y; rb[6]=b1.z; rb[7]=b1.w;
            } else if (WN == 6) {
                float2 b0 = *reinterpret_cast<const float2*>(bp);
                float2 b1 = *reinterpret_cast<const float2*>(bp + 2);
                float2 b2 = *reinterpret_cast<const float2*>(bp + 4);
                rb[0]=b0.x; rb[1]=b0.y; rb[2]=b1.x; rb[3]=b1.y; rb[4]=b2.x; rb[5]=b2.y;
            } else {
                float4 b0 = *reinterpret_cast<const float4*>(bp);
                rb[0]=b0.x; rb[1]=b0.y; rb[2]=b0.z; rb[3]=b0.w;
            }
#pragma unroll
            for (int i = 0; i < 8; i++)
#pragma unroll
                for (int j = 0; j < WN; j++)
                    acc[i][j] = fmaf(ra[i], rb[j], acc[i][j]);
        }

        if (has_next) {
            store_smem(cur ^ 1);   // write other buffer (no hazard with cur reads)
            __syncthreads();       // cur reads done + next buffer visible
            cur ^= 1;
        }
    }

    // epilogue: identical scalar math to the known-good fp32 kernel
#pragma unroll
    for (int i = 0; i < 8; i++) {
        const int r = bm + ty*8 + i;
        if (r >= M) continue;
        float* crow = C + (size_t)r * N + bn + tx*WN;
        const float* rrow = (EPI == 2) ? (res + (size_t)r * N + bn + tx*WN) : nullptr;
        float out[WN];
#pragma unroll
        for (int j = 0; j < WN; j++) {
            float v = acc[i][j] + bias[bn + tx*WN + j];
            if (EPI == 1) v = 0.5f * v * (1.f + erff(v * 0.70710678118654752f));
            if (EPI == 2) v += rrow[j];
            out[j] = v;
        }
        if (WN == 8) {
            *reinterpret_cast<float4*>(crow)     = make_float4(out[0],out[1],out[2],out[3]);
            *reinterpret_cast<float4*>(crow + 4) = make_float4(out[4],out[5],out[6],out[7]);
        } else if (WN == 6) {
            *reinterpret_cast<float2*>(crow)     = make_float2(out[0],out[1]);
            *reinterpret_cast<float2*>(crow + 2) = make_float2(out[2],out[3]);
            *reinterpret_cast<float2*>(crow + 4) = make_float2(out[4],out[5]);
        } else {
            *reinterpret_cast<float4*>(crow)     = make_float4(out[0],out[1],out[2],out[3]);
        }
    }
}

// ---------------- fused attention: one block per (b, h) ----------------
__global__ __launch_bounds__(256) void attn_k(const float* __restrict__ qkv,
                                              float* __restrict__ out, int L) {
    const int h = blockIdx.x, b = blockIdx.y;
    const int tid = threadIdx.x, w = tid >> 5, lane = tid & 31;
    __shared__ float qs[8][64];
    __shared__ float pbuf[8][200];
    const float* base = qkv + (size_t)b * L * (3*DM);
    const int qoff = h*64, koff = DM + h*64, voff = 2*DM + h*64;

    for (int q = w; q < L; q += 8) {
        const float* qrow = base + (size_t)q*(3*DM) + qoff;
        qs[w][lane]    = qrow[lane];
        qs[w][lane+32] = qrow[lane+32];
        __syncwarp();
        float m = -1e30f;
        for (int j = lane; j < L; j += 32) {
            const float* kr = base + (size_t)j*(3*DM) + koff;
            float acc = 0.f;
#pragma unroll
            for (int d = 0; d < 64; d += 4) {
                float4 kv = *reinterpret_cast<const float4*>(kr + d);
                float4 qv = *reinterpret_cast<const float4*>(&qs[w][d]);
                acc += qv.x*kv.x + qv.y*kv.y + qv.z*kv.z + qv.w*kv.w;
            }
            acc *= 0.125f;
            pbuf[w][j] = acc;
            m = fmaxf(m, acc);
        }
        for (int off = 16; off; off >>= 1) m = fmaxf(m, __shfl_xor_sync(0xffffffffu, m, off));
        float sum = 0.f;
        for (int j = lane; j < L; j += 32) {
            float e = expf(pbuf[w][j] - m);
            pbuf[w][j] = e;
            sum += e;
        }
        for (int off = 16; off; off >>= 1) sum += __shfl_xor_sync(0xffffffffu, sum, off);
        float inv = 1.f / sum;
        __syncwarp();
        // PV: j-ascending fp32 chain per output element (order preserved);
        // unrolled x4 only to batch the loads (MLP=4), single accumulator.
        float2 acc2 = make_float2(0.f, 0.f);
        const float* vb = base + voff + lane*2;
        int j = 0;
        for (; j + 4 <= L; j += 4) {
            float p0 = pbuf[w][j+0], p1 = pbuf[w][j+1];
            float p2 = pbuf[w][j+2], p3 = pbuf[w][j+3];
            float2 v0 = *reinterpret_cast<const float2*>(vb + (size_t)(j+0)*(3*DM));
            float2 v1 = *reinterpret_cast<const float2*>(vb + (size_t)(j+1)*(3*DM));
            float2 v2 = *reinterpret_cast<const float2*>(vb + (size_t)(j+2)*(3*DM));
            float2 v3 = *reinterpret_cast<const float2*>(vb + (size_t)(j+3)*(3*DM));
            acc2.x = fmaf(p0, v0.x, acc2.x); acc2.y = fmaf(p0, v0.y, acc2.y);
            acc2.x = fmaf(p1, v1.x, acc2.x); acc2.y = fmaf(p1, v1.y, acc2.y);
            acc2.x = fmaf(p2, v2.x, acc2.x); acc2.y = fmaf(p2, v2.y, acc2.y);
            acc2.x = fmaf(p3, v3.x, acc2.x); acc2.y = fmaf(p3, v3.y, acc2.y);
        }
        for (; j < L; j++) {
            float p = pbuf[w][j];
            float2 v = *reinterpret_cast<const float2*>(vb + (size_t)j*(3*DM));
            acc2.x = fmaf(p, v.x, acc2.x);
            acc2.y = fmaf(p, v.y, acc2.y);
        }
        float* orow = out + ((size_t)b*L + q)*DM + qoff + lane*2;
        orow[0] = acc2.x * inv;
        orow[1] = acc2.y * inv;
        __syncwarp();
    }
}

// ---------------- q0 projection (cls row only, layer-10 q weights) ----------------
__global__ void q0_k(const float* __restrict__ t, const float* __restrict__ w,
                     const float* __restrict__ bias, float* __restrict__ q0) {
    int b = blockIdx.x, tid = threadIdx.x;
    __shared__ float ts[DM];
    const float* tr = t + (size_t)b * LSEQ * DM;
    ts[tid] = tr[tid]; ts[tid+256] = tr[tid+256]; ts[tid+512] = tr[tid+512];
    __syncthreads();
    for (int n = tid; n < DM; n += 256) {
        float acc = bias[n];
        for (int k = 0; k < DM; k++) acc += ts[k] * w[(size_t)k*(3*DM) + n];
        q0[(size_t)b*DM + n] = acc;
    }
}

// ---------------- scoring ----------------
__global__ void score_k(const float* __restrict__ t, const float* __restrict__ kq,
                        const float* __restrict__ q0, const float* __restrict__ imp_w,
                        const float* __restrict__ imp_b, float* __restrict__ O) {
    int b = blockIdx.x, tid = threadIdx.x;
    __shared__ float q0s[DM];
    __shared__ float Ahat[NPATCH];
    __shared__ float red[256];
    q0s[tid] = q0[(size_t)b*DM + tid];
    q0s[tid+256] = q0[(size_t)b*DM + tid+256];
    q0s[tid+512] = q0[(size_t)b*DM + tid+512];
    if (tid < NPATCH) Ahat[tid] = 0.f;
    __syncthreads();
    for (int h = 0; h < NH; h++) {
        float val = -1e30f;
        if (tid < LSEQ) {
            const float* kr = kq + ((size_t)b*LSEQ + tid)*DM + h*64;
            const float* qh = &q0s[h*64];
            float acc = 0.f;
#pragma unroll
            for (int d = 0; d < 64; d++) acc += qh[d] * kr[d];
            val = acc * 0.125f;
        }
        red[tid] = val; __syncthreads();
        for (int s = 128; s; s >>= 1) { if (tid < s) red[tid] = fmaxf(red[tid], red[tid+s]); __syncthreads(); }
        float mv = red[0]; __syncthreads();
        float e = (tid < LSEQ) ? expf(val - mv) : 0.f;
        red[tid] = e; __syncthreads();
        for (int s = 128; s; s >>= 1) { if (tid < s) red[tid] += red[tid+s]; __syncthreads(); }
        float sv = red[0]; __syncthreads();
        if (tid >= 1 && tid < LSEQ) Ahat[tid-1] += e / sv;
        __syncthreads();
    }
    for (int p = tid; p < NPATCH; p += 256) {
        const float* pr = t + ((size_t)b*LSEQ + 1 + p)*DM;
        float dot = 0.f;
        for (int d = 0; d < DM; d++) dot += pr[d] * imp_w[d];
        float z = 1.f / (1.f + expf(-(dot + imp_b[0])));
        O[(size_t)b*NPATCH + p] = Ahat[p] * (1.f + z);
    }
}

// ---------------- top-k=100 of 196, stable ----------------
__global__ void topk_k(const float* __restrict__ O, int* __restrict__ idx) {
    int b = blockIdx.x, lane = threadIdx.x;
    __shared__ float vals[NPATCH];
    for (int j = lane; j < NPATCH; j += 32) vals[j] = O[(size_t)b*NPATCH + j];
    __syncwarp();
    for (int i = 0; i < KTOP; i++) {
        float bv = -1e30f; int bi = NPATCH;
        for (int j = lane; j < NPATCH; j += 32) {
            float v = vals[j];
            if (v > bv || (v == bv && j < bi)) { bv = v; bi = j; }
        }
        for (int off = 16; off; off >>= 1) {
            float ov = __shfl_xor_sync(0xffffffffu, bv, off);
            int   oi = __shfl_xor_sync(0xffffffffu, bi, off);
            if (ov > bv || (ov == bv && oi < bi)) { bv = ov; bi = oi; }
        }
        if (lane == 0) { idx[b*KTOP + i] = bi; vals[bi] = -1e30f; }
        __syncwarp();
    }
}

// ---------------- gather ----------------
__global__ void gather_k(const float* __restrict__ t, const float* __restrict__ pos,
                         const int* __restrict__ idxbuf, float* __restrict__ inp,
                         float* __restrict__ outTop) {
    int idx = blockIdx.x * blockDim.x + threadIdx.x;
    if (idx >= M2 * DM) return;
    int d = idx % DM;
    int m = idx / DM;
    int b = m / LTOP, l = m % LTOP;
    if (l == 0) {
        inp[idx] = t[(size_t)b*LSEQ*DM + d] + pos[d];
    } else {
        int j = idxbuf[b*KTOP + (l-1)];
        float v = t[((size_t)b*LSEQ + 1 + j)*DM + d];
        inp[idx] = v + pos[(size_t)(1+j)*DM + d];
        outTop[((size_t)b*KTOP + (l-1))*DM + d] = v;
    }
}

// ---------------- host ----------------
static inline float* sym(const void* s) {
    void* a = nullptr;
    cudaGetSymbolAddress(&a, s);
    return (float*)a;
}

extern "C" void kernel_launch(void* const* d_in, const int* in_sizes, int n_in,
                              void* d_out, int out_size) {
    const float* x      = (const float*)d_in[0];
    const float* conv_w = (const float*)d_in[1];
    const float* conv_b = (const float*)d_in[2];
    const float* cls    = (const float*)d_in[3];
    const float* pos    = (const float*)d_in[4];
    const float* ln1_s  = (const float*)d_in[5];
    const float* ln1_b  = (const float*)d_in[6];
    const float* qkv_w  = (const float*)d_in[7];
    const float* qkv_b  = (const float*)d_in[8];
    const float* proj_w = (const float*)d_in[9];
    const float* proj_b = (const float*)d_in[10];
    const float* ln2_s  = (const float*)d_in[11];
    const float* ln2_b  = (const float*)d_in[12];
    const float* w1     = (const float*)d_in[13];
    const float* b1     = (const float*)d_in[14];
    const float* w2     = (const float*)d_in[15];
    const float* b2     = (const float*)d_in[16];
    const float* fln_s  = (const float*)d_in[17];
    const float* fln_b  = (const float*)d_in[18];
    const float* imp_w  = (const float*)d_in[19];
    const float* imp_b  = (const float*)d_in[20];

    float* t   = sym(g_t);
    float* lnb = sym(g_ln);
    float* qkv = sym(g_qkv);
    float* att = sym(g_att);
    float* hb  = sym(g_h);
    float* pat = sym(g_pat);
    float* tmp = sym(g_tmp);
    float* kq  = sym(g_kq);
    float* q0  = sym(g_q0);
    float* sc  = sym(g_sc);
    int*   tix = (int*)sym(g_idx);
    float* inp = sym(g_inp);

    float* outMain = (float*)d_out;
    float* outTop  = outMain + (size_t)M2 * DM;

    // ---- patch embedding (TN=128: 294 blocks ~ one perfect wave) ----
    {
        int n = MP * DM;
        im2col_k<<<(n + 255)/256, 256>>>(x, pat);
        gemm_s<0, true, 128><<<dim3(DM/128, (MP+127)/128), 256>>>(
            pat, conv_w, conv_b, nullptr, tmp, MP, DM, DM, DM);
        int n2 = M1 * DM;
        assemble_k<<<(n2 + 255)/256, 256>>>(tmp, cls, pos, t);
    }

    // ---- transformer block ----
    // N-tile per GEMM tuned for wave quantization at 296 CTAs/wave:
    //  qkv  (N=2304): TN=64  -> 36 cols
    //  proj (N=768):  TN=96  -> 8 cols
    //  w1   (N=3072): TN=96  -> 32 cols
    //  w2   (N=768):  TN=96  -> 8 cols
    auto run_block = [&](float* tb, int Lc, int Mr, int i) {
        int mrows = (Mr + 127) / 128;
        dim3 gq(3*DM/64,  mrows);
        dim3 gd(DM/96,    mrows);
        dim3 gh(4*DM/96,  mrows);
        ln_k<<<Mr, 256>>>(tb, ln1_s + (size_t)i*DM, ln1_b + (size_t)i*DM, lnb);
        gemm_s<0, false, 64><<<gq, 256>>>(lnb, qkv_w + (size_t)i*DM*3*DM, qkv_b + (size_t)i*3*DM,
                                          nullptr, qkv, Mr, 3*DM, DM, 3*DM);
        attn_k<<<dim3(NH, BZ), 256>>>(qkv, att, Lc);
        gemm_s<2, false, 96><<<gd, 256>>>(att, proj_w + (size_t)i*DM*DM, proj_b + (size_t)i*DM,
                                          tb, tb, Mr, DM, DM, DM);
        ln_k<<<Mr, 256>>>(tb, ln2_s + (size_t)i*DM, ln2_b + (size_t)i*DM, lnb);
        gemm_s<1, false, 96><<<gh, 256>>>(lnb, w1 + (size_t)i*DM*4*DM, b1 + (size_t)i*4*DM,
                                          nullptr, hb, Mr, 4*DM, DM, 4*DM);
        gemm_s<2, false, 96><<<gd, 256>>>(hb, w2 + (size_t)i*4*DM*DM, b2 + (size_t)i*DM,
                                          tb, tb, Mr, DM, 4*DM, DM);
    };

    for (int i = 0; i < 11; i++) run_block(t, LSEQ, M1, i);

    // ---- scoring with layer-10 weights on raw t (no LN, per reference) ----
    gemm_s<0, false, 96><<<dim3(DM/96, (M1+127)/128), 256>>>(
        t, qkv_w + (size_t)10*DM*3*DM + DM, qkv_b + (size_t)10*3*DM + DM,
        nullptr, kq, M1, DM, DM, 3*DM);
    q0_k<<<BZ, 256>>>(t, qkv_w + (size_t)10*DM*3*DM, qkv_b + (size_t)10*3*DM, q0);
    score_k<<<BZ, 256>>>(t, kq, q0, imp_w, imp_b, sc);
    topk_k<<<BZ, 32>>>(sc, tix);

    // ---- gather top-k, emit top_patches, build final block input ----
    {
        int n = M2 * DM;
        gather_k<<<(n + 255)/256, 256>>>(t, pos, tix, inp, outTop);
    }

    // ---- final transformer block (layer 11) + final LN ----
    run_block(inp, LTOP, M2, 11);
    ln_k<<<M2, 256>>>(inp, fln_s, fln_b, outMain);
}

// round 16
// speedup vs baseline: 1.0209x; 1.0209x over previous
#include <cuda_runtime.h>
#include <math.h>
#include <stdint.h>

// ---------------- problem constants ----------------
#define BZ     32
#define DM     768
#define NH     12
#define DH     64
#define LSEQ   197
#define NPATCH 196
#define LTOP   101
#define KTOP   100
#define M1     (BZ*LSEQ)     // 6304
#define M2     (BZ*LTOP)     // 3232
#define MP     (BZ*NPATCH)   // 6272

// ---------------- device scratch (no allocs allowed) ----------------
__device__ __align__(128) float g_t[M1*DM];
__device__ __align__(128) float g_ln[M1*DM];
__device__ __align__(128) float g_qkv[M1*3*DM];
__device__ __align__(128) float g_att[M1*DM];
__device__ __align__(128) float g_h[M1*4*DM];
__device__ __align__(128) float g_pat[MP*DM];
__device__ __align__(128) float g_tmp[MP*DM];
__device__ __align__(128) float g_kq[M1*DM];
__device__ __align__(128) float g_q0[BZ*DM];
__device__ __align__(128) float g_sc[BZ*NPATCH];
__device__ __align__(128) int   g_idx[BZ*KTOP];
__device__ __align__(128) float g_inp[M2*DM];

// ---------------- im2col: x(B,3,224,224) -> patches (B*196, 768) ----------------
__global__ void im2col_k(const float* __restrict__ x, float* __restrict__ p) {
    int idx = blockIdx.x * blockDim.x + threadIdx.x;
    if (idx >= MP * DM) return;
    int d  = idx % DM;
    int m  = idx / DM;
    int b  = m / NPATCH, pp = m % NPATCH;
    int hp = pp / 14,    wp = pp % 14;
    int c  = d >> 8;
    int rem = d & 255;
    int py = rem >> 4, px = rem & 15;
    p[idx] = x[(((size_t)(b*3 + c)*224 + hp*16 + py))*224 + wp*16 + px];
}

// ---------------- assemble: cls + patches + pos_emb -> t ----------------
__global__ void assemble_k(const float* __restrict__ tmp, const float* __restrict__ cls,
                           const float* __restrict__ pos, float* __restrict__ t) {
    int idx = blockIdx.x * blockDim.x + threadIdx.x;
    if (idx >= M1 * DM) return;
    int d = idx % DM;
    int m = idx / DM;
    int b = m / LSEQ, l = m % LSEQ;
    float v;
    if (l == 0) v = cls[d] + pos[d];
    else        v = tmp[((size_t)b*NPATCH + (l-1))*DM + d] + pos[(size_t)l*DM + d];
    t[idx] = v;
}

// ---------------- layernorm ----------------
__global__ void ln_k(const float* __restrict__ x, const float* __restrict__ gs,
                     const float* __restrict__ bs, float* __restrict__ y) {
    int row = blockIdx.x;
    int tid = threadIdx.x;
    const float* xr = x + (size_t)row * DM;
    float v0 = xr[tid], v1 = xr[tid+256], v2 = xr[tid+512];
    __shared__ float red[256];
    red[tid] = v0 + v1 + v2;
    __syncthreads();
    for (int s = 128; s > 0; s >>= 1) { if (tid < s) red[tid] += red[tid+s]; __syncthreads(); }
    float mean = red[0] * (1.f/768.f);
    __syncthreads();
    float d0 = v0-mean, d1 = v1-mean, d2 = v2-mean;
    red[tid] = d0*d0 + d1*d1 + d2*d2;
    __syncthreads();
    for (int s = 128; s > 0; s >>= 1) { if (tid < s) red[tid] += red[tid+s]; __syncthreads(); }
    float rstd = rsqrtf(red[0] * (1.f/768.f) + 1e-6f);
    float* yr = y + (size_t)row * DM;
    yr[tid]     = d0*rstd*gs[tid]     + bs[tid];
    yr[tid+256] = d1*rstd*gs[tid+256] + bs[tid+256];
    yr[tid+512] = d2*rstd*gs[tid+512] + bs[tid+512];
}

// ---------------- fp32 GEMM: scalar FFMA, double-buffered smem, reg prefetch ----------------
// (round-14 proven config) Bitwise identical to the reference-matching scalar
// pipeline: each output element is a single k-ascending fp32 FMA chain.
// Tile 128x128x16, 256 threads, 8x8 per thread. One __syncthreads per k-tile.
// EPI: 0 = bias, 1 = bias+gelu(exact), 2 = bias+residual
#define KS 132
template<int EPI, bool TRANSB>
__global__ __launch_bounds__(256, 2) void gemm_s(
    const float* __restrict__ A, const float* __restrict__ W,
    const float* __restrict__ bias, const float* __restrict__ res,
    float* __restrict__ C, int M, int N, int K, int ldw)
{
    __shared__ float As[2][16][KS];
    __shared__ float Bs[2][16][KS];
    const int tid = threadIdx.x;
    const int tx = tid & 15;
    const int ty = tid >> 4;
    const int bm = blockIdx.y * 128, bn = blockIdx.x * 128;

    float acc[8][8];
#pragma unroll
    for (int i = 0; i < 8; i++)
#pragma unroll
        for (int j = 0; j < 8; j++) acc[i][j] = 0.f;

    const int rowA = tid >> 1;
    const int kA   = (tid & 1) * 8;
    const int grA  = bm + rowA;
    const bool avalid = (grA < M);
    const int kB = tid >> 4;
    const int nB = (tid & 15) * 8;

    float av[8];
    float bv[8];

    auto load_regs = [&](int k0) {
        if (avalid) {
            const float* ap = A + (size_t)grA * K + k0 + kA;
            float4 a0 = *reinterpret_cast<const float4*>(ap);
            float4 a1 = *reinterpret_cast<const float4*>(ap + 4);
            av[0]=a0.x; av[1]=a0.y; av[2]=a0.z; av[3]=a0.w;
            av[4]=a1.x; av[5]=a1.y; av[6]=a1.z; av[7]=a1.w;
        } else {
#pragma unroll
            for (int q = 0; q < 8; q++) av[q] = 0.f;
        }
        if (!TRANSB) {
            const float* wp = W + (size_t)(k0 + kB) * ldw + bn + nB;
            float4 b0 = *reinterpret_cast<const float4*>(wp);
            float4 b1 = *reinterpret_cast<const float4*>(wp + 4);
            bv[0]=b0.x; bv[1]=b0.y; bv[2]=b0.z; bv[3]=b0.w;
            bv[4]=b1.x; bv[5]=b1.y; bv[6]=b1.z; bv[7]=b1.w;
        } else {
            const float* wp = W + (size_t)(bn + rowA) * ldw + k0 + kA;
            float4 b0 = *reinterpret_cast<const float4*>(wp);
            float4 b1 = *reinterpret_cast<const float4*>(wp + 4);
            bv[0]=b0.x; bv[1]=b0.y; bv[2]=b0.z; bv[3]=b0.w;
            bv[4]=b1.x; bv[5]=b1.y; bv[6]=b1.z; bv[7]=b1.w;
        }
    };
    auto store_smem = [&](int s) {
#pragma unroll
        for (int q = 0; q < 8; q++) As[s][kA+q][rowA] = av[q];
        if (!TRANSB) {
            *reinterpret_cast<float4*>(&Bs[s][kB][nB])     = make_float4(bv[0],bv[1],bv[2],bv[3]);
            *reinterpret_cast<float4*>(&Bs[s][kB][nB + 4]) = make_float4(bv[4],bv[5],bv[6],bv[7]);
        } else {
#pragma unroll
            for (int q = 0; q < 8; q++) Bs[s][kA+q][rowA] = bv[q];
        }
    };

    load_regs(0);
    store_smem(0);
    __syncthreads();

    int cur = 0;
    for (int k0 = 0; k0 < K; k0 += 16) {
        const bool has_next = (k0 + 16 < K);
        if (has_next) load_regs(k0 + 16);

#pragma unroll
        for (int k = 0; k < 16; k++) {
            float4 a0 = *reinterpret_cast<const float4*>(&As[cur][k][ty*8]);
            float4 a1 = *reinterpret_cast<const float4*>(&As[cur][k][ty*8+4]);
            float4 b0 = *reinterpret_cast<const float4*>(&Bs[cur][k][tx*8]);
            float4 b1 = *reinterpret_cast<const float4*>(&Bs[cur][k][tx*8+4]);
            float ra[8] = {a0.x,a0.y,a0.z,a0.w,a1.x,a1.y,a1.z,a1.w};
            float rb[8] = {b0.x,b0.y,b0.z,b0.w,b1.x,b1.y,b1.z,b1.w};
#pragma unroll
            for (int i = 0; i < 8; i++)
#pragma unroll
                for (int j = 0; j < 8; j++)
                    acc[i][j] = fmaf(ra[i], rb[j], acc[i][j]);
        }

        if (has_next) {
            store_smem(cur ^ 1);
            __syncthreads();
            cur ^= 1;
        }
    }

#pragma unroll
    for (int i = 0; i < 8; i++) {
        const int r = bm + ty*8 + i;
        if (r >= M) continue;
        float* crow = C + (size_t)r * N + bn + tx*8;
        const float* rrow = (EPI == 2) ? (res + (size_t)r * N + bn + tx*8) : nullptr;
        float out[8];
#pragma unroll
        for (int j = 0; j < 8; j++) {
            float v = acc[i][j] + bias[bn + tx*8 + j];
            if (EPI == 1) v = 0.5f * v * (1.f + erff(v * 0.70710678118654752f));
            if (EPI == 2) v += rrow[j];
            out[j] = v;
        }
        *reinterpret_cast<float4*>(crow)     = make_float4(out[0],out[1],out[2],out[3]);
        *reinterpret_cast<float4*>(crow + 4) = make_float4(out[4],out[5],out[6],out[7]);
    }
}

// ---------------- 3xTF32 tensor-core GEMM (final block ONLY) ----------------
// Used exclusively for layer 11 on the gathered tokens: that block feeds only
// the `out` tensor (rel_err gate 1e-3), never the top-k ranking. 3xTF32 error
// ~1e-5 << 1e-3. Values validated in round 4 (its failure was rank flips only).
__device__ __forceinline__ uint32_t f2tf32(float f) {
    uint32_t r;
    asm("cvt.rna.tf32.f32 %0, %1;" : "=r"(r) : "f"(f));
    return r;
}
__device__ __forceinline__ void split_tf32(float v, uint32_t& hi, uint32_t& lo) {
    hi = f2tf32(v);
    lo = f2tf32(v - __uint_as_float(hi));
}
__device__ __forceinline__ void mma_tf32(float* c, const uint32_t* a, const uint32_t* b) {
    asm volatile(
        "mma.sync.aligned.m16n8k8.row.col.f32.tf32.tf32.f32 "
        "{%0,%1,%2,%3}, {%4,%5,%6,%7}, {%8,%9}, {%0,%1,%2,%3};"
        : "+f"(c[0]), "+f"(c[1]), "+f"(c[2]), "+f"(c[3])
        : "r"(a[0]), "r"(a[1]), "r"(a[2]), "r"(a[3]), "r"(b[0]), "r"(b[1]));
}

template<int EPI>
__global__ __launch_bounds__(256) void gemm_tc(
    const float* __restrict__ A, const float* __restrict__ W,
    const float* __restrict__ bias, const float* __restrict__ res,
    float* __restrict__ C, int M, int N, int K, int ldw)
{
    __shared__ uint32_t Ah[16][136];
    __shared__ uint32_t Al[16][136];
    __shared__ uint32_t Bh[16][136];
    __shared__ uint32_t Bl[16][136];
    const int tid  = threadIdx.x;
    const int lane = tid & 31;
    const int warp = tid >> 5;
    const int wm = (warp >> 2) * 64;
    const int wn = (warp & 3) * 32;
    const int bm = blockIdx.y * 128, bn = blockIdx.x * 128;

    float acc[4][4][4];
#pragma unroll
    for (int i = 0; i < 4; i++)
#pragma unroll
        for (int j = 0; j < 4; j++)
#pragma unroll
            for (int c = 0; c < 4; c++) acc[i][j][c] = 0.f;

    const int rowA = tid >> 1;
    const int kA   = (tid & 1) * 8;
    const int grA  = bm + rowA;
    const bool avalid = (grA < M);
    const int kB = tid >> 4;
    const int nB = (tid & 15) * 8;

    for (int k0 = 0; k0 < K; k0 += 16) {
        float av[8] = {0.f,0.f,0.f,0.f,0.f,0.f,0.f,0.f};
        if (avalid) {
            const float* ap = A + (size_t)grA * K + k0 + kA;
            float4 a0 = *reinterpret_cast<const float4*>(ap);
            float4 a1 = *reinterpret_cast<const float4*>(ap + 4);
            av[0]=a0.x; av[1]=a0.y; av[2]=a0.z; av[3]=a0.w;
            av[4]=a1.x; av[5]=a1.y; av[6]=a1.z; av[7]=a1.w;
        }
#pragma unroll
        for (int q = 0; q < 8; q++) {
            uint32_t hi, lo; split_tf32(av[q], hi, lo);
            Ah[kA+q][rowA] = hi; Al[kA+q][rowA] = lo;
        }
        {
            const float* wp = W + (size_t)(k0 + kB) * ldw + bn + nB;
            float4 b0 = *reinterpret_cast<const float4*>(wp);
            float4 b1 = *reinterpret_cast<const float4*>(wp + 4);
            float bvv[8] = {b0.x,b0.y,b0.z,b0.w,b1.x,b1.y,b1.z,b1.w};
#pragma unroll
            for (int q = 0; q < 8; q++) {
                uint32_t hi, lo; split_tf32(bvv[q], hi, lo);
                Bh[kB][nB+q] = hi; Bl[kB][nB+q] = lo;
            }
        }
        __syncthreads();

#pragma unroll
        for (int kk = 0; kk < 16; kk += 8) {
            const int kq = kk + (lane & 3);
            const int g  = lane >> 2;
            uint32_t afh[4][4], afl[4][4];
#pragma unroll
            for (int mi = 0; mi < 4; mi++) {
                const int m = wm + mi*16 + g;
                afh[mi][0] = Ah[kq][m];     afl[mi][0] = Al[kq][m];
                afh[mi][1] = Ah[kq][m+8];   afl[mi][1] = Al[kq][m+8];
                afh[mi][2] = Ah[kq+4][m];   afl[mi][2] = Al[kq+4][m];
                afh[mi][3] = Ah[kq+4][m+8]; afl[mi][3] = Al[kq+4][m+8];
            }
#pragma unroll
            for (int ni = 0; ni < 4; ni++) {
                const int n = wn + ni*8 + g;
                uint32_t bfh[2], bfl[2];
                bfh[0] = Bh[kq][n];   bfl[0] = Bl[kq][n];
                bfh[1] = Bh[kq+4][n]; bfl[1] = Bl[kq+4][n];
#pragma unroll
                for (int mi = 0; mi < 4; mi++) {
                    mma_tf32(acc[mi][ni], afh[mi], bfh);
                    mma_tf32(acc[mi][ni], afh[mi], bfl);
                    mma_tf32(acc[mi][ni], afl[mi], bfh);
                }
            }
        }
        __syncthreads();
    }

#pragma unroll
    for (int mi = 0; mi < 4; mi++) {
#pragma unroll
        for (int ni = 0; ni < 4; ni++) {
            const int r  = bm + wm + mi*16 + (lane >> 2);
            const int cc = bn + wn + ni*8 + (lane & 3)*2;
            const float bb0 = bias[cc], bb1 = bias[cc + 1];
#pragma unroll
            for (int half = 0; half < 2; half++) {
                const int rr = r + half*8;
                if (rr >= M) continue;
                float v0 = acc[mi][ni][half*2 + 0] + bb0;
                float v1 = acc[mi][ni][half*2 + 1] + bb1;
                if (EPI == 1) {
                    v0 = 0.5f * v0 * (1.f + erff(v0 * 0.70710678118654752f));
                    v1 = 0.5f * v1 * (1.f + erff(v1 * 0.70710678118654752f));
                }
                if (EPI == 2) {
                    const float* rr_p = res + (size_t)rr * N + cc;
                    v0 += rr_p[0];
                    v1 += rr_p[1];
                }
                *reinterpret_cast<float2*>(C + (size_t)rr * N + cc) = make_float2(v0, v1);
            }
        }
    }
}

// ---------------- fused attention: one block per (b, h) ----------------
__global__ __launch_bounds__(256) void attn_k(const float* __restrict__ qkv,
                                              float* __restrict__ out, int L) {
    const int h = blockIdx.x, b = blockIdx.y;
    const int tid = threadIdx.x, w = tid >> 5, lane = tid & 31;
    __shared__ float qs[8][64];
    __shared__ float pbuf[8][200];
    const float* base = qkv + (size_t)b * L * (3*DM);
    const int qoff = h*64, koff = DM + h*64, voff = 2*DM + h*64;

    for (int q = w; q < L; q += 8) {
        const float* qrow = base + (size_t)q*(3*DM) + qoff;
        qs[w][lane]    = qrow[lane];
        qs[w][lane+32] = qrow[lane+32];
        __syncwarp();
        float m = -1e30f;
        for (int j = lane; j < L; j += 32) {
            const float* kr = base + (size_t)j*(3*DM) + koff;
            float acc = 0.f;
#pragma unroll
            for (int d = 0; d < 64; d += 4) {
                float4 kv = *reinterpret_cast<const float4*>(kr + d);
                float4 qv = *reinterpret_cast<const float4*>(&qs[w][d]);
                acc += qv.x*kv.x + qv.y*kv.y + qv.z*kv.z + qv.w*kv.w;
            }
            acc *= 0.125f;
            pbuf[w][j] = acc;
            m = fmaxf(m, acc);
        }
        for (int off = 16; off; off >>= 1) m = fmaxf(m, __shfl_xor_sync(0xffffffffu, m, off));
        float sum = 0.f;
        for (int j = lane; j < L; j += 32) {
            float e = expf(pbuf[w][j] - m);
            pbuf[w][j] = e;
            sum += e;
        }
        for (int off = 16; off; off >>= 1) sum += __shfl_xor_sync(0xffffffffu, sum, off);
        float inv = 1.f / sum;
        __syncwarp();
        float2 acc2 = make_float2(0.f, 0.f);
        const float* vb = base + voff + lane*2;
        int j = 0;
        for (; j + 4 <= L; j += 4) {
            float p0 = pbuf[w][j+0], p1 = pbuf[w][j+1];
            float p2 = pbuf[w][j+2], p3 = pbuf[w][j+3];
            float2 v0 = *reinterpret_cast<const float2*>(vb + (size_t)(j+0)*(3*DM));
            float2 v1 = *reinterpret_cast<const float2*>(vb + (size_t)(j+1)*(3*DM));
            float2 v2 = *reinterpret_cast<const float2*>(vb + (size_t)(j+2)*(3*DM));
            float2 v3 = *reinterpret_cast<const float2*>(vb + (size_t)(j+3)*(3*DM));
            acc2.x = fmaf(p0, v0.x, acc2.x); acc2.y = fmaf(p0, v0.y, acc2.y);
            acc2.x = fmaf(p1, v1.x, acc2.x); acc2.y = fmaf(p1, v1.y, acc2.y);
            acc2.x = fmaf(p2, v2.x, acc2.x); acc2.y = fmaf(p2, v2.y, acc2.y);
            acc2.x = fmaf(p3, v3.x, acc2.x); acc2.y = fmaf(p3, v3.y, acc2.y);
        }
        for (; j < L; j++) {
            float p = pbuf[w][j];
            float2 v = *reinterpret_cast<const float2*>(vb + (size_t)j*(3*DM));
            acc2.x = fmaf(p, v.x, acc2.x);
            acc2.y = fmaf(p, v.y, acc2.y);
        }
        float* orow = out + ((size_t)b*L + q)*DM + qoff + lane*2;
        orow[0] = acc2.x * inv;
        orow[1] = acc2.y * inv;
        __syncwarp();
    }
}

// ---------------- q0 projection (cls row only, layer-10 q weights) ----------------
__global__ void q0_k(const float* __restrict__ t, const float* __restrict__ w,
                     const float* __restrict__ bias, float* __restrict__ q0) {
    int b = blockIdx.x, tid = threadIdx.x;
    __shared__ float ts[DM];
    const float* tr = t + (size_t)b * LSEQ * DM;
    ts[tid] = tr[tid]; ts[tid+256] = tr[tid+256]; ts[tid+512] = tr[tid+512];
    __syncthreads();
    for (int n = tid; n < DM; n += 256) {
        float acc = bias[n];
        for (int k = 0; k < DM; k++) acc += ts[k] * w[(size_t)k*(3*DM) + n];
        q0[(size_t)b*DM + n] = acc;
    }
}

// ---------------- scoring ----------------
__global__ void score_k(const float* __restrict__ t, const float* __restrict__ kq,
                        const float* __restrict__ q0, const float* __restrict__ imp_w,
                        const float* __restrict__ imp_b, float* __restrict__ O) {
    int b = blockIdx.x, tid = threadIdx.x;
    __shared__ float q0s[DM];
    __shared__ float Ahat[NPATCH];
    __shared__ float red[256];
    q0s[tid] = q0[(size_t)b*DM + tid];
    q0s[tid+256] = q0[(size_t)b*DM + tid+256];
    q0s[tid+512] = q0[(size_t)b*DM + tid+512];
    if (tid < NPATCH) Ahat[tid] = 0.f;
    __syncthreads();
    for (int h = 0; h < NH; h++) {
        float val = -1e30f;
        if (tid < LSEQ) {
            const float* kr = kq + ((size_t)b*LSEQ + tid)*DM + h*64;
            const float* qh = &q0s[h*64];
            float acc = 0.f;
#pragma unroll
            for (int d = 0; d < 64; d++) acc += qh[d] * kr[d];
            val = acc * 0.125f;
        }
        red[tid] = val; __syncthreads();
        for (int s = 128; s; s >>= 1) { if (tid < s) red[tid] = fmaxf(red[tid], red[tid+s]); __syncthreads(); }
        float mv = red[0]; __syncthreads();
        float e = (tid < LSEQ) ? expf(val - mv) : 0.f;
        red[tid] = e; __syncthreads();
        for (int s = 128; s; s >>= 1) { if (tid < s) red[tid] += red[tid+s]; __syncthreads(); }
        float sv = red[0]; __syncthreads();
        if (tid >= 1 && tid < LSEQ) Ahat[tid-1] += e / sv;
        __syncthreads();
    }
    for (int p = tid; p < NPATCH; p += 256) {
        const float* pr = t + ((size_t)b*LSEQ + 1 + p)*DM;
        float dot = 0.f;
        for (int d = 0; d < DM; d++) dot += pr[d] * imp_w[d];
        float z = 1.f / (1.f + expf(-(dot + imp_b[0])));
        O[(size_t)b*NPATCH + p] = Ahat[p] * (1.f + z);
    }
}

// ---------------- top-k=100 of 196, stable ----------------
__global__ void topk_k(const float* __restrict__ O, int* __restrict__ idx) {
    int b = blockIdx.x, lane = threadIdx.x;
    __shared__ float vals[NPATCH];
    for (int j = lane; j < NPATCH; j += 32) vals[j] = O[(size_t)b*NPATCH + j];
    __syncwarp();
    for (int i = 0; i < KTOP; i++) {
        float bv = -1e30f; int bi = NPATCH;
        for (int j = lane; j < NPATCH; j += 32) {
            float v = vals[j];
            if (v > bv || (v == bv && j < bi)) { bv = v; bi = j; }
        }
        for (int off = 16; off; off >>= 1) {
            float ov = __shfl_xor_sync(0xffffffffu, bv, off);
            int   oi = __shfl_xor_sync(0xffffffffu, bi, off);
            if (ov > bv || (ov == bv && oi < bi)) { bv = ov; bi = oi; }
        }
        if (lane == 0) { idx[b*KTOP + i] = bi; vals[bi] = -1e30f; }
        __syncwarp();
    }
}

// ---------------- gather ----------------
__global__ void gather_k(const float* __restrict__ t, const float* __restrict__ pos,
                         const int* __restrict__ idxbuf, float* __restrict__ inp,
                         float* __restrict__ outTop) {
    int idx = blockIdx.x * blockDim.x + threadIdx.x;
    if (idx >= M2 * DM) return;
    int d = idx % DM;
    int m = idx / DM;
    int b = m / LTOP, l = m % LTOP;
    if (l == 0) {
        inp[idx] = t[(size_t)b*LSEQ*DM + d] + pos[d];
    } else {
        int j = idxbuf[b*KTOP + (l-1)];
        float v = t[((size_t)b*LSEQ + 1 + j)*DM + d];
        inp[idx] = v + pos[(size_t)(1+j)*DM + d];
        outTop[((size_t)b*KTOP + (l-1))*DM + d] = v;
    }
}

// ---------------- host ----------------
static inline float* sym(const void* s) {
    void* a = nullptr;
    cudaGetSymbolAddress(&a, s);
    return (float*)a;
}

extern "C" void kernel_launch(void* const* d_in, const int* in_sizes, int n_in,
                              void* d_out, int out_size) {
    const float* x      = (const float*)d_in[0];
    const float* conv_w = (const float*)d_in[1];
    const float* conv_b = (const float*)d_in[2];
    const float* cls    = (const float*)d_in[3];
    const float* pos    = (const float*)d_in[4];
    const float* ln1_s  = (const float*)d_in[5];
    const float* ln1_b  = (const float*)d_in[6];
    const float* qkv_w  = (const float*)d_in[7];
    const float* qkv_b  = (const float*)d_in[8];
    const float* proj_w = (const float*)d_in[9];
    const float* proj_b = (const float*)d_in[10];
    const float* ln2_s  = (const float*)d_in[11];
    const float* ln2_b  = (const float*)d_in[12];
    const float* w1     = (const float*)d_in[13];
    const float* b1     = (const float*)d_in[14];
    const float* w2     = (const float*)d_in[15];
    const float* b2     = (const float*)d_in[16];
    const float* fln_s  = (const float*)d_in[17];
    const float* fln_b  = (const float*)d_in[18];
    const float* imp_w  = (const float*)d_in[19];
    const float* imp_b  = (const float*)d_in[20];

    float* t   = sym(g_t);
    float* lnb = sym(g_ln);
    float* qkv = sym(g_qkv);
    float* att = sym(g_att);
    float* hb  = sym(g_h);
    float* pat = sym(g_pat);
    float* tmp = sym(g_tmp);
    float* kq  = sym(g_kq);
    float* q0  = sym(g_q0);
    float* sc  = sym(g_sc);
    int*   tix = (int*)sym(g_idx);
    float* inp = sym(g_inp);

    float* outMain = (float*)d_out;
    float* outTop  = outMain + (size_t)M2 * DM;

    // ---- patch embedding ----
    {
        int n = MP * DM;
        im2col_k<<<(n + 255)/256, 256>>>(x, pat);
        gemm_s<0, true><<<dim3(DM/128, (MP+127)/128), 256>>>(
            pat, conv_w, conv_b, nullptr, tmp, MP, DM, DM, DM);
        int n2 = M1 * DM;
        assemble_k<<<(n2 + 255)/256, 256>>>(tmp, cls, pos, t);
    }

    // ---- main transformer blocks: exact scalar fp32 (feeds top-k ranking) ----
    auto run_block = [&](float* tb, int Lc, int Mr, int i) {
        dim3 gq(3*DM/128, (Mr+127)/128);
        dim3 gd(DM/128,   (Mr+127)/128);
        dim3 gh(4*DM/128, (Mr+127)/128);
        ln_k<<<Mr, 256>>>(tb, ln1_s + (size_t)i*DM, ln1_b + (size_t)i*DM, lnb);
        gemm_s<0, false><<<gq, 256>>>(lnb, qkv_w + (size_t)i*DM*3*DM, qkv_b + (size_t)i*3*DM,
                                      nullptr, qkv, Mr, 3*DM, DM, 3*DM);
        attn_k<<<dim3(NH, BZ), 256>>>(qkv, att, Lc);
        gemm_s<2, false><<<gd, 256>>>(att, proj_w + (size_t)i*DM*DM, proj_b + (size_t)i*DM,
                                      tb, tb, Mr, DM, DM, DM);
        ln_k<<<Mr, 256>>>(tb, ln2_s + (size_t)i*DM, ln2_b + (size_t)i*DM, lnb);
        gemm_s<1, false><<<gh, 256>>>(lnb, w1 + (size_t)i*DM*4*DM, b1 + (size_t)i*4*DM,
                                      nullptr, hb, Mr, 4*DM, DM, 4*DM);
        gemm_s<2, false><<<gd, 256>>>(hb, w2 + (size_t)i*4*DM*DM, b2 + (size_t)i*DM,
                                      tb, tb, Mr, DM, 4*DM, DM);
    };

    for (int i = 0; i < 11; i++) run_block(t, LSEQ, M1, i);

    // ---- scoring with layer-10 weights on raw t (no LN, per reference) ----
    gemm_s<0, false><<<dim3(DM/128, (M1+127)/128), 256>>>(
        t, qkv_w + (size_t)10*DM*3*DM + DM, qkv_b + (size_t)10*3*DM + DM,
        nullptr, kq, M1, DM, DM, 3*DM);
    q0_k<<<BZ, 256>>>(t, qkv_w + (size_t)10*DM*3*DM, qkv_b + (size_t)10*3*DM, q0);
    score_k<<<BZ, 256>>>(t, kq, q0, imp_w, imp_b, sc);
    topk_k<<<BZ, 32>>>(sc, tix);

    // ---- gather top-k, emit top_patches, build final block input ----
    {
        int n = M2 * DM;
        gather_k<<<(n + 255)/256, 256>>>(t, pos, tix, inp, outTop);
    }

    // ---- final transformer block (layer 11): idx already fixed; feeds only
    // `out` (1e-3 gate). Run its GEMMs on tensor cores (3xTF32, err ~1e-5). ----
    {
        const int i = 11;
        dim3 gq(3*DM/128, (M2+127)/128);
        dim3 gd(DM/128,   (M2+127)/128);
        dim3 gh(4*DM/128, (M2+127)/128);
        ln_k<<<M2, 256>>>(inp, ln1_s + (size_t)i*DM, ln1_b + (size_t)i*DM, lnb);
        gemm_tc<0><<<gq, 256>>>(lnb, qkv_w + (size_t)i*DM*3*DM, qkv_b + (size_t)i*3*DM,
                                nullptr, qkv, M2, 3*DM, DM, 3*DM);
        attn_k<<<dim3(NH, BZ), 256>>>(qkv, att, LTOP);
        gemm_tc<2><<<gd, 256>>>(att, proj_w + (size_t)i*DM*DM, proj_b + (size_t)i*DM,
                                inp, inp, M2, DM, DM, DM);
        ln_k<<<M2, 256>>>(inp, ln2_s + (size_t)i*DM, ln2_b + (size_t)i*DM, lnb);
        gemm_tc<1><<<gh, 256>>>(lnb, w1 + (size_t)i*DM*4*DM, b1 + (size_t)i*4*DM,
                                nullptr, hb, M2, 4*DM, DM, 4*DM);
        gemm_tc<2><<<gd, 256>>>(hb, w2 + (size_t)i*4*DM*DM, b2 + (size_t)i*DM,
                                inp, inp, M2, DM, 4*DM, DM);
    }
    ln_k<<<M2, 256>>>(inp, fln_s, fln_b, outMain);
}

// round 17
// speedup vs baseline: 1.3473x; 1.3197x over previous
#include <cuda_runtime.h>
#include <math.h>
#include <stdint.h>

// ---------------- problem constants ----------------
#define BZ     32
#define DM     768
#define NH     12
#define DH     64
#define LSEQ   197
#define NPATCH 196
#define LTOP   101
#define KTOP   100
#define M1     (BZ*LSEQ)     // 6304
#define M2     (BZ*LTOP)     // 3232
#define MP     (BZ*NPATCH)   // 6272

// attention smem layout (dynamic): K[200][68] + V[200][68] + q[8][64] + p[8][200]
#define AKS    68
#define AROWS  200
#define ATT_SMEM ((2*AROWS*AKS + 8*64 + 8*200) * 4)

// ---------------- device scratch (no allocs allowed) ----------------
__device__ __align__(128) float g_t[M1*DM];
__device__ __align__(128) float g_ln[M1*DM];
__device__ __align__(128) float g_qkv[M1*3*DM];
__device__ __align__(128) float g_att[M1*DM];
__device__ __align__(128) float g_h[M1*4*DM];
__device__ __align__(128) float g_pat[MP*DM];
__device__ __align__(128) float g_tmp[MP*DM];
__device__ __align__(128) float g_kq[M1*DM];
__device__ __align__(128) float g_q0[BZ*DM];
__device__ __align__(128) float g_sc[BZ*NPATCH];
__device__ __align__(128) int   g_idx[BZ*KTOP];
__device__ __align__(128) float g_inp[M2*DM];

// ---------------- im2col: x(B,3,224,224) -> patches (B*196, 768) ----------------
__global__ void im2col_k(const float* __restrict__ x, float* __restrict__ p) {
    int idx = blockIdx.x * blockDim.x + threadIdx.x;
    if (idx >= MP * DM) return;
    int d  = idx % DM;
    int m  = idx / DM;
    int b  = m / NPATCH, pp = m % NPATCH;
    int hp = pp / 14,    wp = pp % 14;
    int c  = d >> 8;
    int rem = d & 255;
    int py = rem >> 4, px = rem & 15;
    p[idx] = x[(((size_t)(b*3 + c)*224 + hp*16 + py))*224 + wp*16 + px];
}

// ---------------- assemble: cls + patches + pos_emb -> t ----------------
__global__ void assemble_k(const float* __restrict__ tmp, const float* __restrict__ cls,
                           const float* __restrict__ pos, float* __restrict__ t) {
    int idx = blockIdx.x * blockDim.x + threadIdx.x;
    if (idx >= M1 * DM) return;
    int d = idx % DM;
    int m = idx / DM;
    int b = m / LSEQ, l = m % LSEQ;
    float v;
    if (l == 0) v = cls[d] + pos[d];
    else        v = tmp[((size_t)b*NPATCH + (l-1))*DM + d] + pos[(size_t)l*DM + d];
    t[idx] = v;
}

// ---------------- layernorm ----------------
__global__ void ln_k(const float* __restrict__ x, const float* __restrict__ gs,
                     const float* __restrict__ bs, float* __restrict__ y) {
    int row = blockIdx.x;
    int tid = threadIdx.x;
    const float* xr = x + (size_t)row * DM;
    float v0 = xr[tid], v1 = xr[tid+256], v2 = xr[tid+512];
    __shared__ float red[256];
    red[tid] = v0 + v1 + v2;
    __syncthreads();
    for (int s = 128; s > 0; s >>= 1) { if (tid < s) red[tid] += red[tid+s]; __syncthreads(); }
    float mean = red[0] * (1.f/768.f);
    __syncthreads();
    float d0 = v0-mean, d1 = v1-mean, d2 = v2-mean;
    red[tid] = d0*d0 + d1*d1 + d2*d2;
    __syncthreads();
    for (int s = 128; s > 0; s >>= 1) { if (tid < s) red[tid] += red[tid+s]; __syncthreads(); }
    float rstd = rsqrtf(red[0] * (1.f/768.f) + 1e-6f);
    float* yr = y + (size_t)row * DM;
    yr[tid]     = d0*rstd*gs[tid]     + bs[tid];
    yr[tid+256] = d1*rstd*gs[tid+256] + bs[tid+256];
    yr[tid+512] = d2*rstd*gs[tid+512] + bs[tid+512];
}

// ---------------- fp32 GEMM: scalar FFMA, double-buffered smem, reg prefetch ----------------
// (round-14 proven config) Bitwise identical to the reference-matching scalar
// pipeline: each output element is a single k-ascending fp32 FMA chain.
// Tile 128x128x16, 256 threads, 8x8 per thread. One __syncthreads per k-tile.
// EPI: 0 = bias, 1 = bias+gelu(exact), 2 = bias+residual
#define KS 132
template<int EPI, bool TRANSB>
__global__ __launch_bounds__(256, 2) void gemm_s(
    const float* __restrict__ A, const float* __restrict__ W,
    const float* __restrict__ bias, const float* __restrict__ res,
    float* __restrict__ C, int M, int N, int K, int ldw)
{
    __shared__ float As[2][16][KS];
    __shared__ float Bs[2][16][KS];
    const int tid = threadIdx.x;
    const int tx = tid & 15;
    const int ty = tid >> 4;
    const int bm = blockIdx.y * 128, bn = blockIdx.x * 128;

    float acc[8][8];
#pragma unroll
    for (int i = 0; i < 8; i++)
#pragma unroll
        for (int j = 0; j < 8; j++) acc[i][j] = 0.f;

    const int rowA = tid >> 1;
    const int kA   = (tid & 1) * 8;
    const int grA  = bm + rowA;
    const bool avalid = (grA < M);
    const int kB = tid >> 4;
    const int nB = (tid & 15) * 8;

    float av[8];
    float bv[8];

    auto load_regs = [&](int k0) {
        if (avalid) {
            const float* ap = A + (size_t)grA * K + k0 + kA;
            float4 a0 = *reinterpret_cast<const float4*>(ap);
            float4 a1 = *reinterpret_cast<const float4*>(ap + 4);
            av[0]=a0.x; av[1]=a0.y; av[2]=a0.z; av[3]=a0.w;
            av[4]=a1.x; av[5]=a1.y; av[6]=a1.z; av[7]=a1.w;
        } else {
#pragma unroll
            for (int q = 0; q < 8; q++) av[q] = 0.f;
        }
        if (!TRANSB) {
            const float* wp = W + (size_t)(k0 + kB) * ldw + bn + nB;
            float4 b0 = *reinterpret_cast<const float4*>(wp);
            float4 b1 = *reinterpret_cast<const float4*>(wp + 4);
            bv[0]=b0.x; bv[1]=b0.y; bv[2]=b0.z; bv[3]=b0.w;
            bv[4]=b1.x; bv[5]=b1.y; bv[6]=b1.z; bv[7]=b1.w;
        } else {
            const float* wp = W + (size_t)(bn + rowA) * ldw + k0 + kA;
            float4 b0 = *reinterpret_cast<const float4*>(wp);
            float4 b1 = *reinterpret_cast<const float4*>(wp + 4);
            bv[0]=b0.x; bv[1]=b0.y; bv[2]=b0.z; bv[3]=b0.w;
            bv[4]=b1.x; bv[5]=b1.y; bv[6]=b1.z; bv[7]=b1.w;
        }
    };
    auto store_smem = [&](int s) {
#pragma unroll
        for (int q = 0; q < 8; q++) As[s][kA+q][rowA] = av[q];
        if (!TRANSB) {
            *reinterpret_cast<float4*>(&Bs[s][kB][nB])     = make_float4(bv[0],bv[1],bv[2],bv[3]);
            *reinterpret_cast<float4*>(&Bs[s][kB][nB + 4]) = make_float4(bv[4],bv[5],bv[6],bv[7]);
        } else {
#pragma unroll
            for (int q = 0; q < 8; q++) Bs[s][kA+q][rowA] = bv[q];
        }
    };

    load_regs(0);
    store_smem(0);
    __syncthreads();

    int cur = 0;
    for (int k0 = 0; k0 < K; k0 += 16) {
        const bool has_next = (k0 + 16 < K);
        if (has_next) load_regs(k0 + 16);

#pragma unroll
        for (int k = 0; k < 16; k++) {
            float4 a0 = *reinterpret_cast<const float4*>(&As[cur][k][ty*8]);
            float4 a1 = *reinterpret_cast<const float4*>(&As[cur][k][ty*8+4]);
            float4 b0 = *reinterpret_cast<const float4*>(&Bs[cur][k][tx*8]);
            float4 b1 = *reinterpret_cast<const float4*>(&Bs[cur][k][tx*8+4]);
            float ra[8] = {a0.x,a0.y,a0.z,a0.w,a1.x,a1.y,a1.z,a1.w};
            float rb[8] = {b0.x,b0.y,b0.z,b0.w,b1.x,b1.y,b1.z,b1.w};
#pragma unroll
            for (int i = 0; i < 8; i++)
#pragma unroll
                for (int j = 0; j < 8; j++)
                    acc[i][j] = fmaf(ra[i], rb[j], acc[i][j]);
        }

        if (has_next) {
            store_smem(cur ^ 1);
            __syncthreads();
            cur ^= 1;
        }
    }

#pragma unroll
    for (int i = 0; i < 8; i++) {
        const int r = bm + ty*8 + i;
        if (r >= M) continue;
        float* crow = C + (size_t)r * N + bn + tx*8;
        const float* rrow = (EPI == 2) ? (res + (size_t)r * N + bn + tx*8) : nullptr;
        float out[8];
#pragma unroll
        for (int j = 0; j < 8; j++) {
            float v = acc[i][j] + bias[bn + tx*8 + j];
            if (EPI == 1) v = 0.5f * v * (1.f + erff(v * 0.70710678118654752f));
            if (EPI == 2) v += rrow[j];
            out[j] = v;
        }
        *reinterpret_cast<float4*>(crow)     = make_float4(out[0],out[1],out[2],out[3]);
        *reinterpret_cast<float4*>(crow + 4) = make_float4(out[4],out[5],out[6],out[7]);
    }
}

// ---------------- 3xTF32 tensor-core GEMM (final block ONLY) ----------------
__device__ __forceinline__ uint32_t f2tf32(float f) {
    uint32_t r;
    asm("cvt.rna.tf32.f32 %0, %1;" : "=r"(r) : "f"(f));
    return r;
}
__device__ __forceinline__ void split_tf32(float v, uint32_t& hi, uint32_t& lo) {
    hi = f2tf32(v);
    lo = f2tf32(v - __uint_as_float(hi));
}
__device__ __forceinline__ void mma_tf32(float* c, const uint32_t* a, const uint32_t* b) {
    asm volatile(
        "mma.sync.aligned.m16n8k8.row.col.f32.tf32.tf32.f32 "
        "{%0,%1,%2,%3}, {%4,%5,%6,%7}, {%8,%9}, {%0,%1,%2,%3};"
        : "+f"(c[0]), "+f"(c[1]), "+f"(c[2]), "+f"(c[3])
        : "r"(a[0]), "r"(a[1]), "r"(a[2]), "r"(a[3]), "r"(b[0]), "r"(b[1]));
}

template<int EPI>
__global__ __launch_bounds__(256) void gemm_tc(
    const float* __restrict__ A, const float* __restrict__ W,
    const float* __restrict__ bias, const float* __restrict__ res,
    float* __restrict__ C, int M, int N, int K, int ldw)
{
    __shared__ uint32_t Ah[16][136];
    __shared__ uint32_t Al[16][136];
    __shared__ uint32_t Bh[16][136];
    __shared__ uint32_t Bl[16][136];
    const int tid  = threadIdx.x;
    const int lane = tid & 31;
    const int warp = tid >> 5;
    const int wm = (warp >> 2) * 64;
    const int wn = (warp & 3) * 32;
    const int bm = blockIdx.y * 128, bn = blockIdx.x * 128;

    float acc[4][4][4];
#pragma unroll
    for (int i = 0; i < 4; i++)
#pragma unroll
        for (int j = 0; j < 4; j++)
#pragma unroll
            for (int c = 0; c < 4; c++) acc[i][j][c] = 0.f;

    const int rowA = tid >> 1;
    const int kA   = (tid & 1) * 8;
    const int grA  = bm + rowA;
    const bool avalid = (grA < M);
    const int kB = tid >> 4;
    const int nB = (tid & 15) * 8;

    for (int k0 = 0; k0 < K; k0 += 16) {
        float av[8] = {0.f,0.f,0.f,0.f,0.f,0.f,0.f,0.f};
        if (avalid) {
            const float* ap = A + (size_t)grA * K + k0 + kA;
            float4 a0 = *reinterpret_cast<const float4*>(ap);
            float4 a1 = *reinterpret_cast<const float4*>(ap + 4);
            av[0]=a0.x; av[1]=a0.y; av[2]=a0.z; av[3]=a0.w;
            av[4]=a1.x; av[5]=a1.y; av[6]=a1.z; av[7]=a1.w;
        }
#pragma unroll
        for (int q = 0; q < 8; q++) {
            uint32_t hi, lo; split_tf32(av[q], hi, lo);
            Ah[kA+q][rowA] = hi; Al[kA+q][rowA] = lo;
        }
        {
            const float* wp = W + (size_t)(k0 + kB) * ldw + bn + nB;
            float4 b0 = *reinterpret_cast<const float4*>(wp);
            float4 b1 = *reinterpret_cast<const float4*>(wp + 4);
            float bvv[8] = {b0.x,b0.y,b0.z,b0.w,b1.x,b1.y,b1.z,b1.w};
#pragma unroll
            for (int q = 0; q < 8; q++) {
                uint32_t hi, lo; split_tf32(bvv[q], hi, lo);
                Bh[kB][nB+q] = hi; Bl[kB][nB+q] = lo;
            }
        }
        __syncthreads();

#pragma unroll
        for (int kk = 0; kk < 16; kk += 8) {
            const int kq = kk + (lane & 3);
            const int g  = lane >> 2;
            uint32_t afh[4][4], afl[4][4];
#pragma unroll
            for (int mi = 0; mi < 4; mi++) {
                const int m = wm + mi*16 + g;
                afh[mi][0] = Ah[kq][m];     afl[mi][0] = Al[kq][m];
                afh[mi][1] = Ah[kq][m+8];   afl[mi][1] = Al[kq][m+8];
                afh[mi][2] = Ah[kq+4][m];   afl[mi][2] = Al[kq+4][m];
                afh[mi][3] = Ah[kq+4][m+8]; afl[mi][3] = Al[kq+4][m+8];
            }
#pragma unroll
            for (int ni = 0; ni < 4; ni++) {
                const int n = wn + ni*8 + g;
                uint32_t bfh[2], bfl[2];
                bfh[0] = Bh[kq][n];   bfl[0] = Bl[kq][n];
                bfh[1] = Bh[kq+4][n]; bfl[1] = Bl[kq+4][n];
#pragma unroll
                for (int mi = 0; mi < 4; mi++) {
                    mma_tf32(acc[mi][ni], afh[mi], bfh);
                    mma_tf32(acc[mi][ni], afh[mi], bfl);
                    mma_tf32(acc[mi][ni], afl[mi], bfh);
                }
            }
        }
        __syncthreads();
    }

#pragma unroll
    for (int mi = 0; mi < 4; mi++) {
#pragma unroll
        for (int ni = 0; ni < 4; ni++) {
            const int r  = bm + wm + mi*16 + (lane >> 2);
            const int cc = bn + wn + ni*8 + (lane & 3)*2;
            const float bb0 = bias[cc], bb1 = bias[cc + 1];
#pragma unroll
            for (int half = 0; half < 2; half++) {
                const int rr = r + half*8;
                if (rr >= M) continue;
                float v0 = acc[mi][ni][half*2 + 0] + bb0;
                float v1 = acc[mi][ni][half*2 + 1] + bb1;
                if (EPI == 1) {
                    v0 = 0.5f * v0 * (1.f + erff(v0 * 0.70710678118654752f));
                    v1 = 0.5f * v1 * (1.f + erff(v1 * 0.70710678118654752f));
                }
                if (EPI == 2) {
                    const float* rr_p = res + (size_t)rr * N + cc;
                    v0 += rr_p[0];
                    v1 += rr_p[1];
                }
                *reinterpret_cast<float2*>(C + (size_t)rr * N + cc) = make_float2(v0, v1);
            }
        }
    }
}

// ---------------- fused attention: one block per (b, h), K/V staged in smem ----------------
// Arithmetic expressions are copied verbatim from the validated gmem version
// (same contraction shape, same j/d order) -> bitwise identical results.
// K/V rows live in smem with stride AKS=68 floats: QK LDS.128 conflict-free
// (bank 4*lane per phase-octet), PV float2 conflict-free.
__global__ __launch_bounds__(256) void attn_k(const float* __restrict__ qkv,
                                              float* __restrict__ out, int L) {
    extern __shared__ float sm[];
    float* Ksm = sm;                          // [AROWS][AKS]
    float* Vsm = sm + AROWS*AKS;              // [AROWS][AKS]
    float* qsm = sm + 2*AROWS*AKS;            // [8][64]
    float* pb  = sm + 2*AROWS*AKS + 8*64;     // [8][200]
    const int h = blockIdx.x, b = blockIdx.y;
    const int tid = threadIdx.x, w = tid >> 5, lane = tid & 31;
    const float* base = qkv + (size_t)b * L * (3*DM);
    const int qoff = h*64, koff = DM + h*64, voff = 2*DM + h*64;

    // stage K and V for this (b,h): coalesced float4 loads
    for (int idx = tid; idx < L*16; idx += 256) {
        int row = idx >> 4, c = (idx & 15) * 4;
        const float* src = base + (size_t)row*(3*DM);
        *reinterpret_cast<float4*>(&Ksm[row*AKS + c]) =
            *reinterpret_cast<const float4*>(src + koff + c);
        *reinterpret_cast<float4*>(&Vsm[row*AKS + c]) =
            *reinterpret_cast<const float4*>(src + voff + c);
    }
    __syncthreads();

    float* qs = qsm + w*64;
    float* pbuf = pb + w*200;

    for (int q = w; q < L; q += 8) {
        const float* qrow = base + (size_t)q*(3*DM) + qoff;
        qs[lane]    = qrow[lane];
        qs[lane+32] = qrow[lane+32];
        __syncwarp();
        float m = -1e30f;
        for (int j = lane; j < L; j += 32) {
            const float* kr = &Ksm[j*AKS];
            float acc = 0.f;
#pragma unroll
            for (int d = 0; d < 64; d += 4) {
                float4 kv = *reinterpret_cast<const float4*>(kr + d);
                float4 qv = *reinterpret_cast<const float4*>(&qs[d]);
                acc += qv.x*kv.x + qv.y*kv.y + qv.z*kv.z + qv.w*kv.w;
            }
            acc *= 0.125f;
            pbuf[j] = acc;
            m = fmaxf(m, acc);
        }
        for (int off = 16; off; off >>= 1) m = fmaxf(m, __shfl_xor_sync(0xffffffffu, m, off));
        float sum = 0.f;
        for (int j = lane; j < L; j += 32) {
            float e = expf(pbuf[j] - m);
            pbuf[j] = e;
            sum += e;
        }
        for (int off = 16; off; off >>= 1) sum += __shfl_xor_sync(0xffffffffu, sum, off);
        float inv = 1.f / sum;
        __syncwarp();
        // PV: j-ascending fp32 chain per output element (order preserved)
        float2 acc2 = make_float2(0.f, 0.f);
        const float* vb = Vsm + lane*2;
        int j = 0;
        for (; j + 4 <= L; j += 4) {
            float p0 = pbuf[j+0], p1 = pbuf[j+1];
            float p2 = pbuf[j+2], p3 = pbuf[j+3];
            float2 v0 = *reinterpret_cast<const float2*>(vb + (j+0)*AKS);
            float2 v1 = *reinterpret_cast<const float2*>(vb + (j+1)*AKS);
            float2 v2 = *reinterpret_cast<const float2*>(vb + (j+2)*AKS);
            float2 v3 = *reinterpret_cast<const float2*>(vb + (j+3)*AKS);
            acc2.x = fmaf(p0, v0.x, acc2.x); acc2.y = fmaf(p0, v0.y, acc2.y);
            acc2.x = fmaf(p1, v1.x, acc2.x); acc2.y = fmaf(p1, v1.y, acc2.y);
            acc2.x = fmaf(p2, v2.x, acc2.x); acc2.y = fmaf(p2, v2.y, acc2.y);
            acc2.x = fmaf(p3, v3.x, acc2.x); acc2.y = fmaf(p3, v3.y, acc2.y);
        }
        for (; j < L; j++) {
            float p = pbuf[j];
            float2 v = *reinterpret_cast<const float2*>(vb + j*AKS);
            acc2.x = fmaf(p, v.x, acc2.x);
            acc2.y = fmaf(p, v.y, acc2.y);
        }
        float* orow = out + ((size_t)b*L + q)*DM + qoff + lane*2;
        orow[0] = acc2.x * inv;
        orow[1] = acc2.y * inv;
        __syncwarp();
    }
}

// ---------------- q0 projection (cls row only, layer-10 q weights) ----------------
__global__ void q0_k(const float* __restrict__ t, const float* __restrict__ w,
                     const float* __restrict__ bias, float* __restrict__ q0) {
    int b = blockIdx.x, tid = threadIdx.x;
    __shared__ float ts[DM];
    const float* tr = t + (size_t)b * LSEQ * DM;
    ts[tid] = tr[tid]; ts[tid+256] = tr[tid+256]; ts[tid+512] = tr[tid+512];
    __syncthreads();
    for (int n = tid; n < DM; n += 256) {
        float acc = bias[n];
        for (int k = 0; k < DM; k++) acc += ts[k] * w[(size_t)k*(3*DM) + n];
        q0[(size_t)b*DM + n] = acc;
    }
}

// ---------------- scoring ----------------
__global__ void score_k(const float* __restrict__ t, const float* __restrict__ kq,
                        const float* __restrict__ q0, const float* __restrict__ imp_w,
                        const float* __restrict__ imp_b, float* __restrict__ O) {
    int b = blockIdx.x, tid = threadIdx.x;
    __shared__ float q0s[DM];
    __shared__ float Ahat[NPATCH];
    __shared__ float red[256];
    q0s[tid] = q0[(size_t)b*DM + tid];
    q0s[tid+256] = q0[(size_t)b*DM + tid+256];
    q0s[tid+512] = q0[(size_t)b*DM + tid+512];
    if (tid < NPATCH) Ahat[tid] = 0.f;
    __syncthreads();
    for (int h = 0; h < NH; h++) {
        float val = -1e30f;
        if (tid < LSEQ) {
            const float* kr = kq + ((size_t)b*LSEQ + tid)*DM + h*64;
            const float* qh = &q0s[h*64];
            float acc = 0.f;
#pragma unroll
            for (int d = 0; d < 64; d++) acc += qh[d] * kr[d];
            val = acc * 0.125f;
        }
        red[tid] = val; __syncthreads();
        for (int s = 128; s; s >>= 1) { if (tid < s) red[tid] = fmaxf(red[tid], red[tid+s]); __syncthreads(); }
        float mv = red[0]; __syncthreads();
        float e = (tid < LSEQ) ? expf(val - mv) : 0.f;
        red[tid] = e; __syncthreads();
        for (int s = 128; s; s >>= 1) { if (tid < s) red[tid] += red[tid+s]; __syncthreads(); }
        float sv = red[0]; __syncthreads();
        if (tid >= 1 && tid < LSEQ) Ahat[tid-1] += e / sv;
        __syncthreads();
    }
    for (int p = tid; p < NPATCH; p += 256) {
        const float* pr = t + ((size_t)b*LSEQ + 1 + p)*DM;
        float dot = 0.f;
        for (int d = 0; d < DM; d++) dot += pr[d] * imp_w[d];
        float z = 1.f / (1.f + expf(-(dot + imp_b[0])));
        O[(size_t)b*NPATCH + p] = Ahat[p] * (1.f + z);
    }
}

// ---------------- top-k=100 of 196, stable ----------------
__global__ void topk_k(const float* __restrict__ O, int* __restrict__ idx) {
    int b = blockIdx.x, lane = threadIdx.x;
    __shared__ float vals[NPATCH];
    for (int j = lane; j < NPATCH; j += 32) vals[j] = O[(size_t)b*NPATCH + j];
    __syncwarp();
    for (int i = 0; i < KTOP; i++) {
        float bv = -1e30f; int bi = NPATCH;
        for (int j = lane; j < NPATCH; j += 32) {
            float v = vals[j];
            if (v > bv || (v == bv && j < bi)) { bv = v; bi = j; }
        }
        for (int off = 16; off; off >>= 1) {
            float ov = __shfl_xor_sync(0xffffffffu, bv, off);
            int   oi = __shfl_xor_sync(0xffffffffu, bi, off);
            if (ov > bv || (ov == bv && oi < bi)) { bv = ov; bi = oi; }
        }
        if (lane == 0) { idx[b*KTOP + i] = bi; vals[bi] = -1e30f; }
        __syncwarp();
    }
}

// ---------------- gather ----------------
__global__ void gather_k(const float* __restrict__ t, const float* __restrict__ pos,
                         const int* __restrict__ idxbuf, float* __restrict__ inp,
                         float* __restrict__ outTop) {
    int idx = blockIdx.x * blockDim.x + threadIdx.x;
    if (idx >= M2 * DM) return;
    int d = idx % DM;
    int m = idx / DM;
    int b = m / LTOP, l = m % LTOP;
    if (l == 0) {
        inp[idx] = t[(size_t)b*LSEQ*DM + d] + pos[d];
    } else {
        int j = idxbuf[b*KTOP + (l-1)];
        float v = t[((size_t)b*LSEQ + 1 + j)*DM + d];
        inp[idx] = v + pos[(size_t)(1+j)*DM + d];
        outTop[((size_t)b*KTOP + (l-1))*DM + d] = v;
    }
}

// ---------------- host ----------------
static inline float* sym(const void* s) {
    void* a = nullptr;
    cudaGetSymbolAddress(&a, s);
    return (float*)a;
}

extern "C" void kernel_launch(void* const* d_in, const int* in_sizes, int n_in,
                              void* d_out, int out_size) {
    const float* x      = (const float*)d_in[0];
    const float* conv_w = (const float*)d_in[1];
    const float* conv_b = (const float*)d_in[2];
    const float* cls    = (const float*)d_in[3];
    const float* pos    = (const float*)d_in[4];
    const float* ln1_s  = (const float*)d_in[5];
    const float* ln1_b  = (const float*)d_in[6];
    const float* qkv_w  = (const float*)d_in[7];
    const float* qkv_b  = (const float*)d_in[8];
    const float* proj_w = (const float*)d_in[9];
    const float* proj_b = (const float*)d_in[10];
    const float* ln2_s  = (const float*)d_in[11];
    const float* ln2_b  = (const float*)d_in[12];
    const float* w1     = (const float*)d_in[13];
    const float* b1     = (const float*)d_in[14];
    const float* w2     = (const float*)d_in[15];
    const float* b2     = (const float*)d_in[16];
    const float* fln_s  = (const float*)d_in[17];
    const float* fln_b  = (const float*)d_in[18];
    const float* imp_w  = (const float*)d_in[19];
    const float* imp_b  = (const float*)d_in[20];

    float* t   = sym(g_t);
    float* lnb = sym(g_ln);
    float* qkv = sym(g_qkv);
    float* att = sym(g_att);
    float* hb  = sym(g_h);
    float* pat = sym(g_pat);
    float* tmp = sym(g_tmp);
    float* kq  = sym(g_kq);
    float* q0  = sym(g_q0);
    float* sc  = sym(g_sc);
    int*   tix = (int*)sym(g_idx);
    float* inp = sym(g_inp);

    float* outMain = (float*)d_out;
    float* outTop  = outMain + (size_t)M2 * DM;

    // allow the attention kernel its 117KB dynamic smem (idempotent, non-stream)
    static bool attr_set = false;
    if (!attr_set) {
        cudaFuncSetAttribute(attn_k, cudaFuncAttributeMaxDynamicSharedMemorySize, ATT_SMEM);
        attr_set = true;
    }

    // ---- patch embedding ----
    {
        int n = MP * DM;
        im2col_k<<<(n + 255)/256, 256>>>(x, pat);
        gemm_s<0, true><<<dim3(DM/128, (MP+127)/128), 256>>>(
            pat, conv_w, conv_b, nullptr, tmp, MP, DM, DM, DM);
        int n2 = M1 * DM;
        assemble_k<<<(n2 + 255)/256, 256>>>(tmp, cls, pos, t);
    }

    // ---- main transformer blocks: exact scalar fp32 (feeds top-k ranking) ----
    auto run_block = [&](float* tb, int Lc, int Mr, int i) {
        dim3 gq(3*DM/128, (Mr+127)/128);
        dim3 gd(DM/128,   (Mr+127)/128);
        dim3 gh(4*DM/128, (Mr+127)/128);
        ln_k<<<Mr, 256>>>(tb, ln1_s + (size_t)i*DM, ln1_b + (size_t)i*DM, lnb);
        gemm_s<0, false><<<gq, 256>>>(lnb, qkv_w + (size_t)i*DM*3*DM, qkv_b + (size_t)i*3*DM,
                                      nullptr, qkv, Mr, 3*DM, DM, 3*DM);
        attn_k<<<dim3(NH, BZ), 256, ATT_SMEM>>>(qkv, att, Lc);
        gemm_s<2, false><<<gd, 256>>>(att, proj_w + (size_t)i*DM*DM, proj_b + (size_t)i*DM,
                                      tb, tb, Mr, DM, DM, DM);
        ln_k<<<Mr, 256>>>(tb, ln2_s + (size_t)i*DM, ln2_b + (size_t)i*DM, lnb);
        gemm_s<1, false><<<gh, 256>>>(lnb, w1 + (size_t)i*DM*4*DM, b1 + (size_t)i*4*DM,
                                      nullptr, hb, Mr, 4*DM, DM, 4*DM);
        gemm_s<2, false><<<gd, 256>>>(hb, w2 + (size_t)i*4*DM*DM, b2 + (size_t)i*DM,
                                      tb, tb, Mr, DM, 4*DM, DM);
    };

    for (int i = 0; i < 11; i++) run_block(t, LSEQ, M1, i);

    // ---- scoring with layer-10 weights on raw t (no LN, per reference) ----
    gemm_s<0, false><<<dim3(DM/128, (M1+127)/128), 256>>>(
        t, qkv_w + (size_t)10*DM*3*DM + DM, qkv_b + (size_t)10*3*DM + DM,
        nullptr, kq, M1, DM, DM, 3*DM);
    q0_k<<<BZ, 256>>>(t, qkv_w + (size_t)10*DM*3*DM, qkv_b + (size_t)10*3*DM, q0);
    score_k<<<BZ, 256>>>(t, kq, q0, imp_w, imp_b, sc);
    topk_k<<<BZ, 32>>>(sc, tix);

    // ---- gather top-k, emit top_patches, build final block input ----
    {
        int n = M2 * DM;
        gather_k<<<(n + 255)/256, 256>>>(t, pos, tix, inp, outTop);
    }

    // ---- final transformer block (layer 11): idx already fixed; feeds only
    // `out` (1e-3 gate). Run its GEMMs on tensor cores (3xTF32, err ~1e-5). ----
    {
        const int i = 11;
        dim3 gq(3*DM/128, (M2+127)/128);
        dim3 gd(DM/128,   (M2+127)/128);
        dim3 gh(4*DM/128, (M2+127)/128);
        ln_k<<<M2, 256>>>(inp, ln1_s + (size_t)i*DM, ln1_b + (size_t)i*DM, lnb);
        gemm_tc<0><<<gq, 256>>>(lnb, qkv_w + (size_t)i*DM*3*DM, qkv_b + (size_t)i*3*DM,
                                nullptr, qkv, M2, 3*DM, DM, 3*DM);
        attn_k<<<dim3(NH, BZ), 256, ATT_SMEM>>>(qkv, att, LTOP);
        gemm_tc<2><<<gd, 256>>>(att, proj_w + (size_t)i*DM*DM, proj_b + (size_t)i*DM,
                                inp, inp, M2, DM, DM, DM);
        ln_k<<<M2, 256>>>(inp, ln2_s + (size_t)i*DM, ln2_b + (size_t)i*DM, lnb);
        gemm_tc<1><<<gh, 256>>>(lnb, w1 + (size_t)i*DM*4*DM, b1 + (size_t)i*4*DM,
                                nullptr, hb, M2, 4*DM, DM, 4*DM);
        gemm_tc<2><<<gd, 256>>>(hb, w2 + (size_t)i*4*DM*DM, b2 + (size_t)i*DM,
                                inp, inp, M2, DM, 4*DM, DM);
    }
    ln_k<<<M2, 256>>>(inp, fln_s, fln_b, outMain);
}